// round 7
// baseline (speedup 1.0000x reference)
#include <cuda_runtime.h>

// PCLSTM: B=20, C=395, H=10, T=8192.
// Fused single kernel: blocks [0,10) each run TWO interleaved batch recurrences
// (one warp, batches 2b and 2b+1) so the two dependency chains hide each other's
// stalls under in-order issue. Blocks [10,650) compute gate pre-activations for
// one (chunk-of-256-t, batch) tile and publish per-chunk ready flags.
// Activations via tanh.approx.f32:
//   sigmoid(z) = 0.5 + 0.5*tanh(0.5*z)  (0.5 folded into pre/Wh weights)
// c0 = b_init (W_init mathematically unused).

#define Bk 20
#define Ck 395
#define Hk 10
#define Tk 8192
#define GIN 800
#define CHUNK 32
#define NCHUNKS 32     // Tk / 256
#define TCH 256
#define NRECB 10       // recurrence blocks (2 batches each)

typedef unsigned long long ull;

// pre buffer: [b][t][h] float4 (x=.5*zf, y=.5*zi, z=zu, w=.5*zo), + pad for prefetch overrun
__device__ __align__(16) float4 g_pre[(size_t)Bk * Tk * 10 + 256];
__device__ int g_ready[NCHUNKS];

__device__ __forceinline__ ull pack2(float a, float b) {
    ull r; asm("mov.b64 %0, {%1,%2};" : "=l"(r) : "f"(a), "f"(b)); return r;
}
__device__ __forceinline__ void unpack2(ull v, float& a, float& b) {
    asm("mov.b64 {%0,%1}, %2;" : "=f"(a), "=f"(b) : "l"(v));
}
__device__ __forceinline__ void ffma2(ull& d, ull a, ull b) {
    asm("fma.rn.f32x2 %0, %1, %2, %0;" : "+l"(d) : "l"(a), "l"(b));
}
__device__ __forceinline__ float tanhf_a(float x) {
    float r; asm("tanh.approx.f32 %0, %1;" : "=f"(r) : "f"(x)); return r;
}
__device__ __forceinline__ int ld_acq(const int* p) {
    int v; asm volatile("ld.acquire.gpu.b32 %0, [%1];" : "=r"(v) : "l"(p) : "memory");
    return v;
}

__global__ void zero_flags() {
    if (threadIdx.x < NCHUNKS) g_ready[threadIdx.x] = 0;
}

// ---------------------------------------------------------------------------
// One LSTM step. Lanes 0-9 (mirror 20-29): owner of unit j, compute f,i,u + c,h.
// Lanes 10-19: compute o for unit j=lane-10; shipped to owner via shfl (off-chain).
// pf pre-scaled: x=0.5*zf, y=0.5*zi, z=zu, w=0.5*zo. Wh similarly pre-scaled.
// ---------------------------------------------------------------------------
__device__ __forceinline__ float step_fn(
    float4 pf, bool owner, int osrc, float& hval, float& cval,
    const ull* wA, const ull* wB, const ull* wC)
{
    float hk[10];
    #pragma unroll
    for (int k = 0; k < 10; ++k) hk[k] = __shfl_sync(0xffffffffu, hval, k);
    ull hp[5];
    #pragma unroll
    for (int q = 0; q < 5; ++q) hp[q] = pack2(hk[2 * q], hk[2 * q + 1]);

    float p0 = owner ? pf.x : pf.w;
    ull A  = pack2(p0,   0.0f);
    ull Bv = pack2(pf.y, 0.0f);
    ull Cv = pack2(pf.z, 0.0f);
    #pragma unroll
    for (int q = 0; q < 5; ++q) {
        ffma2(A,  hp[q], wA[q]);
        ffma2(Bv, hp[q], wB[q]);
        ffma2(Cv, hp[q], wC[q]);
    }
    float alo, ahi, blo, bhi, clo, chi;
    unpack2(A, alo, ahi); unpack2(Bv, blo, bhi); unpack2(Cv, clo, chi);
    float z0 = alo + ahi, z1 = blo + bhi, z2 = clo + chi;

    // slot0: sigmoid -> f (owner) / o (o-lane)
    float t0 = tanhf_a(z0);
    float r0 = fmaf(0.5f, t0, 0.5f);
    float osh = __shfl_sync(0xffffffffu, r0, osrc);   // o arrives off-chain

    float ti = tanhf_a(z1);
    float tg = tanhf_a(z2);
    float iv = fmaf(0.5f, ti, 0.5f);
    float ig = iv * tg;

    cval = fmaf(cval, r0, ig);
    float tc = tanhf_a(cval);
    hval = osh * tc;
    return hval;
}

__device__ __forceinline__ void spin_chunk(int k) {
    #pragma unroll 1
    while (ld_acq(&g_ready[k]) < Bk) { }
}

// ---------------------------------------------------------------------------
__global__ __launch_bounds__(128) void pclstm_fused(
    const float* __restrict__ x, const float* __restrict__ y,
    const float* __restrict__ Wf, const float* __restrict__ bf,
    const float* __restrict__ Wi, const float* __restrict__ bi,
    const float* __restrict__ Wu, const float* __restrict__ bu,
    const float* __restrict__ Wo, const float* __restrict__ bo,
    const float* __restrict__ b_init, float* __restrict__ out)
{
    __shared__ __align__(16) ull sWx[CHUNK * 40];
    __shared__ __align__(16) ull sWy[CHUNK * 40];

    const int tid = threadIdx.x;
    const int bx  = blockIdx.x;

    if (bx < NRECB) {
        // ========== recurrence role: 1 warp, 2 interleaved batches ==========
        if (tid >= 32) return;
        const int lane = tid;
        const int j = lane % 10;
        const bool owner = (lane < 10) || (lane >= 20);
        const int osrc = 10 + j;
        const int bA = 2 * bx;
        const int bB = 2 * bx + 1;

        const float* WAp = owner ? Wf : Wo;
        float wa[10], wb[10], wc[10];
        #pragma unroll
        for (int k = 0; k < 10; ++k) {
            wa[k] = 0.5f * WAp[j * GIN + Ck + k];
            wb[k] = owner ? (0.5f * Wi[j * GIN + Ck + k]) : 0.0f;
            wc[k] = owner ? Wu[j * GIN + Ck + k] : 0.0f;
        }
        ull wA2[5], wB2[5], wC2[5];
        #pragma unroll
        for (int q = 0; q < 5; ++q) {
            wA2[q] = pack2(wa[2 * q], wa[2 * q + 1]);
            wB2[q] = pack2(wb[2 * q], wb[2 * q + 1]);
            wC2[q] = pack2(wc[2 * q], wc[2 * q + 1]);
        }

        float hA = 0.0f, cA = b_init[j];
        float hB = 0.0f, cB = b_init[j];

        const float4* ppA = g_pre + (size_t)bA * Tk * 10 + j;
        const float4* ppB = g_pre + (size_t)bB * Tk * 10 + j;
        float* opA = out + ((size_t)bA * Hk + j) * Tk;
        float* opB = out + ((size_t)bB * Hk + j) * Tk;

        spin_chunk(0);
        float4 cA0 = ppA[0],  cA1 = ppA[10], cA2 = ppA[20], cA3 = ppA[30];
        float4 nA0 = ppA[40], nA1 = ppA[50], nA2 = ppA[60], nA3 = ppA[70];
        float4 cB0 = ppB[0],  cB1 = ppB[10], cB2 = ppB[20], cB3 = ppB[30];
        float4 nB0 = ppB[40], nB1 = ppB[50], nB2 = ppB[60], nB3 = ppB[70];

        #pragma unroll 1
        for (int kc = 0; kc < NCHUNKS; ++kc) {
            spin_chunk(kc < NCHUNKS - 1 ? kc + 1 : NCHUNKS - 1);
            const int tend = kc * TCH + TCH;
            #pragma unroll 1
            for (int t0 = kc * TCH; t0 < tend; t0 += 4) {
                float a0 = step_fn(cA0, owner, osrc, hA, cA, wA2, wB2, wC2);
                float b0 = step_fn(cB0, owner, osrc, hB, cB, wA2, wB2, wC2);
                float a1 = step_fn(cA1, owner, osrc, hA, cA, wA2, wB2, wC2);
                float b1 = step_fn(cB1, owner, osrc, hB, cB, wA2, wB2, wC2);
                float a2 = step_fn(cA2, owner, osrc, hA, cA, wA2, wB2, wC2);
                float b2 = step_fn(cB2, owner, osrc, hB, cB, wA2, wB2, wC2);
                float a3 = step_fn(cA3, owner, osrc, hA, cA, wA2, wB2, wC2);
                float b3 = step_fn(cB3, owner, osrc, hB, cB, wA2, wB2, wC2);

                if (lane < 10) {
                    *(float4*)(opA + t0) = make_float4(a0, a1, a2, a3);
                    *(float4*)(opB + t0) = make_float4(b0, b1, b2, b3);
                }

                cA0 = nA0; cA1 = nA1; cA2 = nA2; cA3 = nA3;
                cB0 = nB0; cB1 = nB1; cB2 = nB2; cB3 = nB3;
                const float4* npA = ppA + (size_t)(t0 + 8) * 10;   // pad covers overrun
                const float4* npB = ppB + (size_t)(t0 + 8) * 10;
                nA0 = npA[0]; nA1 = npA[10]; nA2 = npA[20]; nA3 = npA[30];
                nB0 = npB[0]; nB1 = npB[10]; nB2 = npB[20]; nB3 = npB[30];
            }
        }
        if (lane < 10) {
            out[(size_t)Bk * Hk * Tk + bA * Hk + j] = cA;
            out[(size_t)Bk * Hk * Tk + bB * Hk + j] = cB;
        }
        return;
    }

    // ================= GEMM role: one (chunk, batch) tile =================
    const int g     = bx - NRECB;
    const int b     = g % Bk;        // batch varies fastest -> chunk-major completion
    const int chunk = g / Bk;
    const int t     = chunk * TCH + tid * 2;

    ull acc[40];
    #pragma unroll
    for (int h = 0; h < Hk; ++h) {
        acc[h]      = pack2(bf[h], bf[h]);
        acc[10 + h] = pack2(bi[h], bi[h]);
        acc[20 + h] = pack2(bu[h], bu[h]);
        acc[30 + h] = pack2(bo[h], bo[h]);
    }

    for (int c0 = 0; c0 < Ck; c0 += CHUNK) {
        const int clen = min(CHUNK, Ck - c0);
        __syncthreads();
        for (int idx = tid; idx < clen * 40; idx += 128) {
            int cl = idx / 40;
            int gh = idx - cl * 40;
            int gg = gh / 10;
            int h  = gh - gg * 10;
            const float* Wgp = (gg == 0) ? Wf : ((gg == 1) ? Wi : ((gg == 2) ? Wu : Wo));
            int col = c0 + cl;
            float wx  = Wgp[h * GIN + col];
            float wyv = Wgp[h * GIN + (Ck + Hk) + col];
            sWx[cl * 40 + gh] = pack2(wx, wx);
            sWy[cl * 40 + gh] = pack2(wyv, wyv);
        }
        __syncthreads();

        const float* xp = x + ((size_t)(b * Ck + c0)) * Tk + t;
        const float* yp = y + ((size_t)(b * Ck + c0)) * Tk + t;
        for (int cl = 0; cl < clen; ++cl) {
            float2 xv = *(const float2*)xp;
            float ya = (t > 0) ? yp[-1] : 0.0f;   // y_prev[t]   = y[t-1]
            float yb = yp[0];                     // y_prev[t+1] = y[t]
            ull X2 = pack2(xv.x, xv.y);
            ull Y2 = pack2(ya, yb);
            const ulonglong2* wx2 = (const ulonglong2*)&sWx[cl * 40];
            const ulonglong2* wy2 = (const ulonglong2*)&sWy[cl * 40];
            #pragma unroll
            for (int q = 0; q < 20; ++q) {
                ulonglong2 wv = wx2[q];
                ffma2(acc[2 * q],     X2, wv.x);
                ffma2(acc[2 * q + 1], X2, wv.y);
            }
            #pragma unroll
            for (int q = 0; q < 20; ++q) {
                ulonglong2 wv = wy2[q];
                ffma2(acc[2 * q],     Y2, wv.x);
                ffma2(acc[2 * q + 1], Y2, wv.y);
            }
            xp += Tk; yp += Tk;
        }
    }

    // Epilogue: fold sigmoid 0.5 scaling (f,i,o); u unscaled. Store [t][h][gate] float4.
    float4* outp = g_pre + ((size_t)b * Tk + t) * 10;
    #pragma unroll
    for (int h = 0; h < Hk; ++h) {
        float f0, f1, i0, i1, u0, u1, o0, o1;
        unpack2(acc[h],      f0, f1);
        unpack2(acc[10 + h], i0, i1);
        unpack2(acc[20 + h], u0, u1);
        unpack2(acc[30 + h], o0, o1);
        outp[h]      = make_float4(0.5f * f0, 0.5f * i0, u0, 0.5f * o0);
        outp[10 + h] = make_float4(0.5f * f1, 0.5f * i1, u1, 0.5f * o1);
    }

    __threadfence();
    __syncthreads();
    if (tid == 0) atomicAdd(&g_ready[chunk], 1);
}

// ---------------------------------------------------------------------------
extern "C" void kernel_launch(void* const* d_in, const int* in_sizes, int n_in,
                              void* d_out, int out_size)
{
    const float* x      = (const float*)d_in[0];
    const float* y      = (const float*)d_in[1];
    const float* Wf     = (const float*)d_in[2];
    const float* bf     = (const float*)d_in[3];
    const float* Wi     = (const float*)d_in[4];
    const float* bi     = (const float*)d_in[5];
    const float* Wu     = (const float*)d_in[6];
    const float* bu     = (const float*)d_in[7];
    const float* Wo     = (const float*)d_in[8];
    const float* bo     = (const float*)d_in[9];
    // d_in[10] = W_init: unused (c0 = 0 @ W_init.T + b_init == b_init)
    const float* b_init = (const float*)d_in[11];
    float* out = (float*)d_out;
    (void)in_sizes; (void)n_in; (void)out_size;

    zero_flags<<<1, 32>>>();
    pclstm_fused<<<NRECB + NCHUNKS * Bk, 128>>>(x, y, Wf, bf, Wi, bi, Wu, bu, Wo, bo,
                                                b_init, out);
}

// round 10
// speedup vs baseline: 1.2472x; 1.2472x over previous
#include <cuda_runtime.h>

// PCLSTM: B=20, C=395, H=10, T=8192.
// Fused: blocks [0,20) = recurrence (1 warp, 1 batch each); blocks [20,660) =
// gate pre-activation GEMM tiles ((chunk-of-256-t) x batch), publishing per-chunk
// ready flags that the recurrence warps chase.
// Lane roles in rec warp: 0-9 f-gate + c/h chain (unit j=lane), 10-19 o-gate,
// 20-29 i-gate; u-gate on owners' second FFMA slot. sigmoid via
// 0.5+0.5*tanh(0.5z) with the 0.5 folded into pre/Wh. c0 = b_init.

#define Bk 20
#define Ck 395
#define Hk 10
#define Tk 8192
#define GIN 800
#define CHUNK 32
#define NCHUNKS 32     // Tk / 256
#define TCH 256

typedef unsigned long long ull;

// pre buffer: [b][t][h] float4 (x=.5*zf, y=.5*zi, z=zu, w=.5*zo) + pad for prefetch overrun
__device__ __align__(16) float4 g_pre[(size_t)Bk * Tk * 10 + 512];
__device__ int g_ready[NCHUNKS];
__device__ __align__(16) float g_dump[64];   // sink for non-owner lane stores

__device__ __forceinline__ ull pack2(float a, float b) {
    ull r; asm("mov.b64 %0, {%1,%2};" : "=l"(r) : "f"(a), "f"(b)); return r;
}
__device__ __forceinline__ void unpack2(ull v, float& a, float& b) {
    asm("mov.b64 {%0,%1}, %2;" : "=f"(a), "=f"(b) : "l"(v));
}
__device__ __forceinline__ void ffma2(ull& d, ull a, ull b) {
    asm("fma.rn.f32x2 %0, %1, %2, %0;" : "+l"(d) : "l"(a), "l"(b));
}
__device__ __forceinline__ float tanhf_a(float x) {
    float r; asm("tanh.approx.f32 %0, %1;" : "=f"(r) : "f"(x)); return r;
}
__device__ __forceinline__ int ld_acq(const int* p) {
    int v; asm volatile("ld.acquire.gpu.b32 %0, [%1];" : "=r"(v) : "l"(p) : "memory");
    return v;
}

__global__ void zero_flags() {
    if (threadIdx.x < NCHUNKS) g_ready[threadIdx.x] = 0;
}

// ---------------------------------------------------------------------------
// One LSTM step. role 0: f + c/h chain; role 1: o; role 2: i. u on slot B.
// pf pre-scaled: x=.5*zf, y=.5*zi, z=zu, w=.5*zo.
// ---------------------------------------------------------------------------
__device__ __forceinline__ float step_fn(
    float4 pf, int role, int osrc, int isrc, float& hval, float& cval,
    const ull* wA, const ull* wB)
{
    float hk[10];
    #pragma unroll
    for (int k = 0; k < 10; ++k) hk[k] = __shfl_sync(0xffffffffu, hval, k);
    ull hp[5];
    #pragma unroll
    for (int q = 0; q < 5; ++q) hp[q] = pack2(hk[2 * q], hk[2 * q + 1]);

    float p0 = (role == 0) ? pf.x : ((role == 1) ? pf.w : pf.y);
    ull A  = pack2(p0,   0.0f);
    ull Bv = pack2(pf.z, 0.0f);          // u (owners)
    #pragma unroll
    for (int q = 0; q < 5; ++q) {
        ffma2(A,  hp[q], wA[q]);
        ffma2(Bv, hp[q], wB[q]);
    }
    float alo, ahi, blo, bhi;
    unpack2(A, alo, ahi); unpack2(Bv, blo, bhi);
    float z0 = alo + ahi, z2 = blo + bhi;

    float t0 = tanhf_a(z0);
    float r0 = fmaf(0.5f, t0, 0.5f);     // f / o / i by role
    float osh = __shfl_sync(0xffffffffu, r0, osrc);   // o, off-chain
    float ish = __shfl_sync(0xffffffffu, r0, isrc);   // i, overlaps tanh(zu)
    float tg = tanhf_a(z2);              // g = tanh(zu)
    float ig = ish * tg;

    cval = fmaf(cval, r0, ig);           // owners: r0 = f
    float tc = tanhf_a(cval);
    hval = osh * tc;
    return hval;
}

__device__ __forceinline__ void spin_chunk(int k) {
    #pragma unroll 1
    while (ld_acq(&g_ready[k]) < Bk) { }
}

#define LOAD8(dst, base, tt)                                             \
    do {                                                                 \
        const float4* _p = (base) + (size_t)(tt) * 10;                   \
        dst##0 = _p[0];  dst##1 = _p[10]; dst##2 = _p[20]; dst##3 = _p[30]; \
        dst##4 = _p[40]; dst##5 = _p[50]; dst##6 = _p[60]; dst##7 = _p[70]; \
    } while (0)

// ---------------------------------------------------------------------------
__global__ __launch_bounds__(128) void pclstm_fused(
    const float* __restrict__ x, const float* __restrict__ y,
    const float* __restrict__ Wf, const float* __restrict__ bf,
    const float* __restrict__ Wi, const float* __restrict__ bi,
    const float* __restrict__ Wu, const float* __restrict__ bu,
    const float* __restrict__ Wo, const float* __restrict__ bo,
    const float* __restrict__ b_init, float* __restrict__ out)
{
    __shared__ __align__(16) ull sWx[CHUNK * 40];
    __shared__ __align__(16) ull sWy[CHUNK * 40];

    const int tid = threadIdx.x;
    const int bx  = blockIdx.x;

    if (bx < Bk) {
        // ================= recurrence role (1 warp per batch) =================
        if (tid >= 32) return;
        const int lane = tid;
        const int j = lane % 10;
        const int role = (lane < 10) ? 0 : ((lane < 20) ? 1 : 2);
        const int osrc = 10 + j;
        const int isrc = 20 + j;

        const float* WAp = (role == 0) ? Wf : ((role == 1) ? Wo : Wi);
        float wa[10], wb[10];
        #pragma unroll
        for (int k = 0; k < 10; ++k) {
            wa[k] = 0.5f * WAp[j * GIN + Ck + k];
            wb[k] = Wu[j * GIN + Ck + k];
        }
        ull wA2[5], wB2[5];
        #pragma unroll
        for (int q = 0; q < 5; ++q) {
            wA2[q] = pack2(wa[2 * q], wa[2 * q + 1]);
            wB2[q] = pack2(wb[2 * q], wb[2 * q + 1]);
        }

        float hval = 0.0f;
        float cval = b_init[j];

        const float4* pp = g_pre + (size_t)bx * Tk * 10 + j;
        float* op = out + ((size_t)bx * Hk + j) * Tk;
        const bool owner = (role == 0);

        spin_chunk(0);
        float4 A0, A1, A2, A3, A4, A5, A6, A7;
        float4 B0, B1, B2, B3, B4, B5, B6, B7;
        LOAD8(A, pp, 0);
        LOAD8(B, pp, 8);

        #pragma unroll 1
        for (int kc = 0; kc < NCHUNKS; ++kc) {
            spin_chunk(kc < NCHUNKS - 1 ? kc + 1 : NCHUNKS - 1);
            const int tend = kc * TCH + TCH;
            #pragma unroll 1
            for (int t0 = kc * TCH; t0 < tend; t0 += 16) {
                // ---- half 1: steps t0..t0+7 from A; refill A <- t0+16 ----
                float h0 = step_fn(A0, role, osrc, isrc, hval, cval, wA2, wB2);
                float h1 = step_fn(A1, role, osrc, isrc, hval, cval, wA2, wB2);
                float h2 = step_fn(A2, role, osrc, isrc, hval, cval, wA2, wB2);
                float h3 = step_fn(A3, role, osrc, isrc, hval, cval, wA2, wB2);
                float h4 = step_fn(A4, role, osrc, isrc, hval, cval, wA2, wB2);
                float h5 = step_fn(A5, role, osrc, isrc, hval, cval, wA2, wB2);
                float h6 = step_fn(A6, role, osrc, isrc, hval, cval, wA2, wB2);
                float h7 = step_fn(A7, role, osrc, isrc, hval, cval, wA2, wB2);
                {
                    float4* s0 = owner ? (float4*)(op + t0)     : (float4*)g_dump;
                    float4* s1 = owner ? (float4*)(op + t0 + 4) : (float4*)(g_dump + 4);
                    *s0 = make_float4(h0, h1, h2, h3);
                    *s1 = make_float4(h4, h5, h6, h7);
                }
                LOAD8(A, pp, t0 + 16);   // pad covers end-of-time overrun

                // ---- half 2: steps t0+8..t0+15 from B; refill B <- t0+24 ----
                h0 = step_fn(B0, role, osrc, isrc, hval, cval, wA2, wB2);
                h1 = step_fn(B1, role, osrc, isrc, hval, cval, wA2, wB2);
                h2 = step_fn(B2, role, osrc, isrc, hval, cval, wA2, wB2);
                h3 = step_fn(B3, role, osrc, isrc, hval, cval, wA2, wB2);
                h4 = step_fn(B4, role, osrc, isrc, hval, cval, wA2, wB2);
                h5 = step_fn(B5, role, osrc, isrc, hval, cval, wA2, wB2);
                h6 = step_fn(B6, role, osrc, isrc, hval, cval, wA2, wB2);
                h7 = step_fn(B7, role, osrc, isrc, hval, cval, wA2, wB2);
                {
                    float4* s0 = owner ? (float4*)(op + t0 + 8)  : (float4*)g_dump;
                    float4* s1 = owner ? (float4*)(op + t0 + 12) : (float4*)(g_dump + 4);
                    *s0 = make_float4(h0, h1, h2, h3);
                    *s1 = make_float4(h4, h5, h6, h7);
                }
                LOAD8(B, pp, t0 + 24);   // pad covers end-of-time overrun
            }
        }
        if (owner) out[(size_t)Bk * Hk * Tk + bx * Hk + j] = cval;
        return;
    }

    // ================= GEMM role: one (chunk, batch) tile =================
    const int g     = bx - Bk;
    const int b     = g % Bk;        // batch varies fastest -> chunk-major completion
    const int chunk = g / Bk;
    const int t     = chunk * TCH + tid * 2;

    ull acc[40];
    #pragma unroll
    for (int h = 0; h < Hk; ++h) {
        acc[h]      = pack2(bf[h], bf[h]);
        acc[10 + h] = pack2(bi[h], bi[h]);
        acc[20 + h] = pack2(bu[h], bu[h]);
        acc[30 + h] = pack2(bo[h], bo[h]);
    }

    for (int c0 = 0; c0 < Ck; c0 += CHUNK) {
        const int clen = min(CHUNK, Ck - c0);
        __syncthreads();
        for (int idx = tid; idx < clen * 40; idx += 128) {
            int cl = idx / 40;
            int gh = idx - cl * 40;
            int gg = gh / 10;
            int h  = gh - gg * 10;
            const float* Wgp = (gg == 0) ? Wf : ((gg == 1) ? Wi : ((gg == 2) ? Wu : Wo));
            int col = c0 + cl;
            float wx  = Wgp[h * GIN + col];
            float wyv = Wgp[h * GIN + (Ck + Hk) + col];
            sWx[cl * 40 + gh] = pack2(wx, wx);
            sWy[cl * 40 + gh] = pack2(wyv, wyv);
        }
        __syncthreads();

        const float* xp = x + ((size_t)(b * Ck + c0)) * Tk + t;
        const float* yp = y + ((size_t)(b * Ck + c0)) * Tk + t;
        for (int cl = 0; cl < clen; ++cl) {
            float2 xv = *(const float2*)xp;
            float ya = (t > 0) ? yp[-1] : 0.0f;   // y_prev[t]   = y[t-1]
            float yb = yp[0];                     // y_prev[t+1] = y[t]
            ull X2 = pack2(xv.x, xv.y);
            ull Y2 = pack2(ya, yb);
            const ulonglong2* wx2 = (const ulonglong2*)&sWx[cl * 40];
            const ulonglong2* wy2 = (const ulonglong2*)&sWy[cl * 40];
            #pragma unroll
            for (int q = 0; q < 20; ++q) {
                ulonglong2 wv = wx2[q];
                ffma2(acc[2 * q],     X2, wv.x);
                ffma2(acc[2 * q + 1], X2, wv.y);
            }
            #pragma unroll
            for (int q = 0; q < 20; ++q) {
                ulonglong2 wv = wy2[q];
                ffma2(acc[2 * q],     Y2, wv.x);
                ffma2(acc[2 * q + 1], Y2, wv.y);
            }
            xp += Tk; yp += Tk;
        }
    }

    // Epilogue: fold sigmoid 0.5 scaling (f,i,o); u unscaled. Store [t][h][gate] float4.
    float4* outp = g_pre + ((size_t)b * Tk + t) * 10;
    #pragma unroll
    for (int h = 0; h < Hk; ++h) {
        float f0, f1, i0, i1, u0, u1, o0, o1;
        unpack2(acc[h],      f0, f1);
        unpack2(acc[10 + h], i0, i1);
        unpack2(acc[20 + h], u0, u1);
        unpack2(acc[30 + h], o0, o1);
        outp[h]      = make_float4(0.5f * f0, 0.5f * i0, u0, 0.5f * o0);
        outp[10 + h] = make_float4(0.5f * f1, 0.5f * i1, u1, 0.5f * o1);
    }

    __threadfence();
    __syncthreads();
    if (tid == 0) atomicAdd(&g_ready[chunk], 1);
}

// ---------------------------------------------------------------------------
extern "C" void kernel_launch(void* const* d_in, const int* in_sizes, int n_in,
                              void* d_out, int out_size)
{
    const float* x      = (const float*)d_in[0];
    const float* y      = (const float*)d_in[1];
    const float* Wf     = (const float*)d_in[2];
    const float* bf     = (const float*)d_in[3];
    const float* Wi     = (const float*)d_in[4];
    const float* bi     = (const float*)d_in[5];
    const float* Wu     = (const float*)d_in[6];
    const float* bu     = (const float*)d_in[7];
    const float* Wo     = (const float*)d_in[8];
    const float* bo     = (const float*)d_in[9];
    // d_in[10] = W_init: unused (c0 = 0 @ W_init.T + b_init == b_init)
    const float* b_init = (const float*)d_in[11];
    float* out = (float*)d_out;
    (void)in_sizes; (void)n_in; (void)out_size;

    zero_flags<<<1, 32>>>();
    pclstm_fused<<<Bk + NCHUNKS * Bk, 128>>>(x, y, Wf, bf, Wi, bi, Wu, bu, Wo, bo,
                                             b_init, out);
}

// round 12
// speedup vs baseline: 1.4419x; 1.1561x over previous
#include <cuda_runtime.h>

// PCLSTM: B=20, C=395, H=10, T=8192.
// Fused: blocks [0,20) = recurrence (1 warp, 1 batch each); blocks [20,660) =
// gate pre-activation GEMM tiles ((chunk-of-256-t) x batch), publishing per-chunk
// ready flags that the recurrence warps chase.
// Recurrence: lane j (mirrors at j=lane%10) computes ALL FOUR gates for unit j
// locally via gate-paired f32x2 dots -- acc1=(0.5zf,0.5zi), acc2=(zu,0.5zo) --
// so the only cross-lane traffic per step is the h broadcast (10 shfl).
// sigmoid via 0.5+0.5*tanh(0.5z), 0.5 folded into pre/Wh. c0 = b_init.

#define Bk 20
#define Ck 395
#define Hk 10
#define Tk 8192
#define GIN 800
#define CHUNK 32
#define NCHUNKS 32     // Tk / 256
#define TCH 256

typedef unsigned long long ull;

// pre buffer: [b][t][h] float4 (x=.5*zf, y=.5*zi, z=zu, w=.5*zo) + pad for prefetch overrun
__device__ __align__(16) float4 g_pre[(size_t)Bk * Tk * 10 + 512];
__device__ int g_ready[NCHUNKS];
__device__ __align__(16) float g_dump[64];   // sink for non-owner lane stores

__device__ __forceinline__ ull pack2(float a, float b) {
    ull r; asm("mov.b64 %0, {%1,%2};" : "=l"(r) : "f"(a), "f"(b)); return r;
}
__device__ __forceinline__ ull dup2(float a) {
    ull r; asm("mov.b64 %0, {%1,%1};" : "=l"(r) : "f"(a)); return r;
}
__device__ __forceinline__ void unpack2(ull v, float& a, float& b) {
    asm("mov.b64 {%0,%1}, %2;" : "=f"(a), "=f"(b) : "l"(v));
}
__device__ __forceinline__ void ffma2(ull& d, ull a, ull b) {
    asm("fma.rn.f32x2 %0, %1, %2, %0;" : "+l"(d) : "l"(a), "l"(b));
}
__device__ __forceinline__ ull add2(ull a, ull b) {
    ull r; asm("add.rn.f32x2 %0, %1, %2;" : "=l"(r) : "l"(a), "l"(b)); return r;
}
__device__ __forceinline__ float tanhf_a(float x) {
    float r; asm("tanh.approx.f32 %0, %1;" : "=f"(r) : "f"(x)); return r;
}
__device__ __forceinline__ int ld_acq(const int* p) {
    int v; asm volatile("ld.acquire.gpu.b32 %0, [%1];" : "=r"(v) : "l"(p) : "memory");
    return v;
}

__global__ void zero_flags() {
    if (threadIdx.x < NCHUNKS) g_ready[threadIdx.x] = 0;
}

// ---------------------------------------------------------------------------
// One LSTM step, fully lane-local except the h broadcast.
// pf pre-scaled: x=.5*zf, y=.5*zi, z=zu, w=.5*zo.
// wfi[k] = (0.5*Whf[j][k], 0.5*Whi[j][k]); wuo[k] = (Whu[j][k], 0.5*Who[j][k]).
// ---------------------------------------------------------------------------
__device__ __forceinline__ float step_all(
    float4 pf, float& hval, float& cval, const ull* wfi, const ull* wuo)
{
    ull hd[10];
    #pragma unroll
    for (int k = 0; k < 10; ++k) {
        float hk = __shfl_sync(0xffffffffu, hval, k);
        hd[k] = dup2(hk);
    }

    ull a1 = pack2(pf.x, pf.y);   // (0.5*zf, 0.5*zi)
    ull a2 = pack2(pf.z, pf.w);   // (zu, 0.5*zo)
    ull b1 = dup2(0.0f);
    ull b2 = dup2(0.0f);
    #pragma unroll
    for (int q = 0; q < 5; ++q) {
        ffma2(a1, hd[2 * q],     wfi[2 * q]);
        ffma2(b1, hd[2 * q + 1], wfi[2 * q + 1]);
        ffma2(a2, hd[2 * q],     wuo[2 * q]);
        ffma2(b2, hd[2 * q + 1], wuo[2 * q + 1]);
    }
    a1 = add2(a1, b1);
    a2 = add2(a2, b2);
    float zf, zi, zu, zo;
    unpack2(a1, zf, zi);
    unpack2(a2, zu, zo);

    float ti = tanhf_a(zi);           // sigmoid args pre-halved
    float tg = tanhf_a(zu);
    float tf = tanhf_a(zf);
    float to = tanhf_a(zo);
    float iv = fmaf(0.5f, ti, 0.5f);
    float ig = iv * tg;
    float fv = fmaf(0.5f, tf, 0.5f);
    cval = fmaf(cval, fv, ig);
    float ov = fmaf(0.5f, to, 0.5f);
    float tc = tanhf_a(cval);
    hval = ov * tc;
    return hval;
}

__device__ __forceinline__ void spin_chunk(int k) {
    #pragma unroll 1
    while (ld_acq(&g_ready[k]) < Bk) { }
}

#define LOAD8(dst, base, tt)                                             \
    do {                                                                 \
        const float4* _p = (base) + (size_t)(tt) * 10;                   \
        dst##0 = _p[0];  dst##1 = _p[10]; dst##2 = _p[20]; dst##3 = _p[30]; \
        dst##4 = _p[40]; dst##5 = _p[50]; dst##6 = _p[60]; dst##7 = _p[70]; \
    } while (0)

// ---------------------------------------------------------------------------
__global__ __launch_bounds__(128) void pclstm_fused(
    const float* __restrict__ x, const float* __restrict__ y,
    const float* __restrict__ Wf, const float* __restrict__ bf,
    const float* __restrict__ Wi, const float* __restrict__ bi,
    const float* __restrict__ Wu, const float* __restrict__ bu,
    const float* __restrict__ Wo, const float* __restrict__ bo,
    const float* __restrict__ b_init, float* __restrict__ out)
{
    __shared__ __align__(16) ull sWx[CHUNK * 40];
    __shared__ __align__(16) ull sWy[CHUNK * 40];

    const int tid = threadIdx.x;
    const int bx  = blockIdx.x;

    if (bx < Bk) {
        // ================= recurrence role (1 warp per batch) =================
        if (tid >= 32) return;
        const int lane = tid;
        const int j = lane % 10;
        const bool owner = (lane < 10);

        ull wfi[10], wuo[10];
        #pragma unroll
        for (int k = 0; k < 10; ++k) {
            wfi[k] = pack2(0.5f * Wf[j * GIN + Ck + k], 0.5f * Wi[j * GIN + Ck + k]);
            wuo[k] = pack2(Wu[j * GIN + Ck + k],        0.5f * Wo[j * GIN + Ck + k]);
        }

        float hval = 0.0f;
        float cval = b_init[j];

        const float4* pp = g_pre + (size_t)bx * Tk * 10 + j;
        float* op = out + ((size_t)bx * Hk + j) * Tk;

        spin_chunk(0);
        float4 A0, A1, A2, A3, A4, A5, A6, A7;
        float4 B0, B1, B2, B3, B4, B5, B6, B7;
        LOAD8(A, pp, 0);
        LOAD8(B, pp, 8);

        #pragma unroll 1
        for (int kc = 0; kc < NCHUNKS; ++kc) {
            spin_chunk(kc < NCHUNKS - 1 ? kc + 1 : NCHUNKS - 1);
            const int tend = kc * TCH + TCH;
            #pragma unroll 1
            for (int t0 = kc * TCH; t0 < tend; t0 += 16) {
                // ---- half 1: steps t0..t0+7 from A; refill A <- t0+16 ----
                float h0 = step_all(A0, hval, cval, wfi, wuo);
                float h1 = step_all(A1, hval, cval, wfi, wuo);
                float h2 = step_all(A2, hval, cval, wfi, wuo);
                float h3 = step_all(A3, hval, cval, wfi, wuo);
                float h4 = step_all(A4, hval, cval, wfi, wuo);
                float h5 = step_all(A5, hval, cval, wfi, wuo);
                float h6 = step_all(A6, hval, cval, wfi, wuo);
                float h7 = step_all(A7, hval, cval, wfi, wuo);
                {
                    float4* s0 = owner ? (float4*)(op + t0)     : (float4*)g_dump;
                    float4* s1 = owner ? (float4*)(op + t0 + 4) : (float4*)(g_dump + 4);
                    *s0 = make_float4(h0, h1, h2, h3);
                    *s1 = make_float4(h4, h5, h6, h7);
                }
                LOAD8(A, pp, t0 + 16);   // pad covers end-of-time overrun

                // ---- half 2: steps t0+8..t0+15 from B; refill B <- t0+24 ----
                h0 = step_all(B0, hval, cval, wfi, wuo);
                h1 = step_all(B1, hval, cval, wfi, wuo);
                h2 = step_all(B2, hval, cval, wfi, wuo);
                h3 = step_all(B3, hval, cval, wfi, wuo);
                h4 = step_all(B4, hval, cval, wfi, wuo);
                h5 = step_all(B5, hval, cval, wfi, wuo);
                h6 = step_all(B6, hval, cval, wfi, wuo);
                h7 = step_all(B7, hval, cval, wfi, wuo);
                {
                    float4* s0 = owner ? (float4*)(op + t0 + 8)  : (float4*)g_dump;
                    float4* s1 = owner ? (float4*)(op + t0 + 12) : (float4*)(g_dump + 4);
                    *s0 = make_float4(h0, h1, h2, h3);
                    *s1 = make_float4(h4, h5, h6, h7);
                }
                LOAD8(B, pp, t0 + 24);   // pad covers end-of-time overrun
            }
        }
        if (owner) out[(size_t)Bk * Hk * Tk + bx * Hk + j] = cval;
        return;
    }

    // ================= GEMM role: one (chunk, batch) tile =================
    const int g     = bx - Bk;
    const int b     = g % Bk;        // batch varies fastest -> chunk-major completion
    const int chunk = g / Bk;
    const int t     = chunk * TCH + tid * 2;

    ull acc[40];
    #pragma unroll
    for (int h = 0; h < Hk; ++h) {
        acc[h]      = pack2(bf[h], bf[h]);
        acc[10 + h] = pack2(bi[h], bi[h]);
        acc[20 + h] = pack2(bu[h], bu[h]);
        acc[30 + h] = pack2(bo[h], bo[h]);
    }

    for (int c0 = 0; c0 < Ck; c0 += CHUNK) {
        const int clen = min(CHUNK, Ck - c0);
        __syncthreads();
        for (int idx = tid; idx < clen * 40; idx += 128) {
            int cl = idx / 40;
            int gh = idx - cl * 40;
            int gg = gh / 10;
            int h  = gh - gg * 10;
            const float* Wgp = (gg == 0) ? Wf : ((gg == 1) ? Wi : ((gg == 2) ? Wu : Wo));
            int col = c0 + cl;
            float wx  = Wgp[h * GIN + col];
            float wyv = Wgp[h * GIN + (Ck + Hk) + col];
            sWx[cl * 40 + gh] = pack2(wx, wx);
            sWy[cl * 40 + gh] = pack2(wyv, wyv);
        }
        __syncthreads();

        const float* xp = x + ((size_t)(b * Ck + c0)) * Tk + t;
        const float* yp = y + ((size_t)(b * Ck + c0)) * Tk + t;
        for (int cl = 0; cl < clen; ++cl) {
            float2 xv = *(const float2*)xp;
            float ya = (t > 0) ? yp[-1] : 0.0f;   // y_prev[t]   = y[t-1]
            float yb = yp[0];                     // y_prev[t+1] = y[t]
            ull X2 = pack2(xv.x, xv.y);
            ull Y2 = pack2(ya, yb);
            const ulonglong2* wx2 = (const ulonglong2*)&sWx[cl * 40];
            const ulonglong2* wy2 = (const ulonglong2*)&sWy[cl * 40];
            #pragma unroll
            for (int q = 0; q < 20; ++q) {
                ulonglong2 wv = wx2[q];
                ffma2(acc[2 * q],     X2, wv.x);
                ffma2(acc[2 * q + 1], X2, wv.y);
            }
            #pragma unroll
            for (int q = 0; q < 20; ++q) {
                ulonglong2 wv = wy2[q];
                ffma2(acc[2 * q],     Y2, wv.x);
                ffma2(acc[2 * q + 1], Y2, wv.y);
            }
            xp += Tk; yp += Tk;
        }
    }

    // Epilogue: fold sigmoid 0.5 scaling (f,i,o); u unscaled. Store [t][h][gate] float4.
    float4* outp = g_pre + ((size_t)b * Tk + t) * 10;
    #pragma unroll
    for (int h = 0; h < Hk; ++h) {
        float f0, f1, i0, i1, u0, u1, o0, o1;
        unpack2(acc[h],      f0, f1);
        unpack2(acc[10 + h], i0, i1);
        unpack2(acc[20 + h], u0, u1);
        unpack2(acc[30 + h], o0, o1);
        outp[h]      = make_float4(0.5f * f0, 0.5f * i0, u0, 0.5f * o0);
        outp[10 + h] = make_float4(0.5f * f1, 0.5f * i1, u1, 0.5f * o1);
    }

    __threadfence();
    __syncthreads();
    if (tid == 0) atomicAdd(&g_ready[chunk], 1);
}

// ---------------------------------------------------------------------------
extern "C" void kernel_launch(void* const* d_in, const int* in_sizes, int n_in,
                              void* d_out, int out_size)
{
    const float* x      = (const float*)d_in[0];
    const float* y      = (const float*)d_in[1];
    const float* Wf     = (const float*)d_in[2];
    const float* bf     = (const float*)d_in[3];
    const float* Wi     = (const float*)d_in[4];
    const float* bi     = (const float*)d_in[5];
    const float* Wu     = (const float*)d_in[6];
    const float* bu     = (const float*)d_in[7];
    const float* Wo     = (const float*)d_in[8];
    const float* bo     = (const float*)d_in[9];
    // d_in[10] = W_init: unused (c0 = 0 @ W_init.T + b_init == b_init)
    const float* b_init = (const float*)d_in[11];
    float* out = (float*)d_out;
    (void)in_sizes; (void)n_in; (void)out_size;

    zero_flags<<<1, 32>>>();
    pclstm_fused<<<Bk + NCHUNKS * Bk, 128>>>(x, y, Wf, bf, Wi, bi, Wu, bu, Wo, bo,
                                             b_init, out);
}